// round 10
// baseline (speedup 1.0000x reference)
#include <cuda_runtime.h>
#include <cstdint>

// CRF Viterbi decode: B=128, T=1024, K=128. One CTA (128 threads) per batch.
// Forward (R6-proven): thread per output column j; 32x broadcast LDS.128 of
// state, 64x add.rn.f32x2 vs transitions in 64 u64 regs, 8-acc FMNMX tree.
// History = PRE-logit maxima h_t (h_0 = 0), one STG per step.
// Backtrack (R9): tags[t] = first i with (h_t[i]+logit_t[i])+T[i][cur] ==
// h_{t+1}[cur] (stored exact max) -> equality scan with 4 parallel ballots,
// NO reduction ops. Exact first-index tie-break == jnp.argmax semantics.
// h + logit rows double-buffered into SMEM via cp.async. One-hot f32 out.

#define BB 128
#define TT 1024
#define KK 128
#define TC_STRIDE 132
#define NTHREADS 128
#define BR 32                 // backtrack steps per staged block

// 64 MB pre-logit history scratch
__device__ float g_h[(size_t)BB * TT * KK];

struct __align__(16) SmemLayout {
    float transC[KK * TC_STRIDE];   // transC[j*132 + i] = T[i][j]
    float spad[2][KK];              // double-buffered live state (post-logit)
    float logit[2][16][KK];         // double-buffered fwd logit staging
    float hblk[2][(BR + 1) * KK];   // backtrack h rows [lo .. hi+1]
    float lblk[2][BR * KK];         // backtrack logit rows [lo .. hi]
    int   tags[TT];
    int   lasttag;
};

__device__ __forceinline__ unsigned smem_u32(const void* p) {
    return (unsigned)__cvta_generic_to_shared(p);
}
__device__ __forceinline__ void cp_async16(unsigned dst, const void* src) {
    asm volatile("cp.async.cg.shared.global [%0], [%1], 16;" :: "r"(dst), "l"(src));
}
__device__ __forceinline__ unsigned f32_mono_u32(float x) {
    unsigned b = __float_as_uint(x);
    return b ^ (unsigned)(((int)b >> 31) | 0x80000000);
}

__global__ void __launch_bounds__(NTHREADS, 1)
crf_viterbi_kernel(const float* __restrict__ logits,
                   const int*   __restrict__ lens,
                   const float* __restrict__ trans,
                   float*       __restrict__ out)
{
    extern __shared__ char smraw[];
    SmemLayout& s = *reinterpret_cast<SmemLayout*>(smraw);

    const int b    = blockIdx.x;
    const int tid  = threadIdx.x;
    const int w    = tid >> 5;         // 4 warps
    const int lane = tid & 31;
    const int j    = tid;              // output column owned by this thread
    const int len  = lens[b];

    // ---- transC staging (vectorized read, strided scalar STS; init-only) ----
    for (int idx = tid * 4; idx < KK * KK; idx += NTHREADS * 4) {
        float4 v = *reinterpret_cast<const float4*>(trans + idx);
        int i  = idx >> 7;
        int jj = idx & (KK - 1);
        s.transC[(jj + 0) * TC_STRIDE + i] = v.x;
        s.transC[(jj + 1) * TC_STRIDE + i] = v.y;
        s.transC[(jj + 2) * TC_STRIDE + i] = v.z;
        s.transC[(jj + 3) * TC_STRIDE + i] = v.w;
    }

    // ---- init: state_0 = logits[b,0,:], h_0 = 0 ----
    {
        float v = logits[((size_t)b * TT) * KK + tid];
        s.spad[0][tid] = v;
        g_h[((size_t)b * TT) * KK + tid] = 0.0f;
    }

    // ---- prologue: stage logit rows 1..16 into buffer 0 ----
    {
        const float* base = logits + (size_t)b * TT * KK + lane * 4;
        #pragma unroll
        for (int k = 0; k < 4; ++k) {
            int ridx = w + 4 * k;          // row-in-epoch 0..15
            int r = 1 + ridx;  if (r > TT - 1) r = TT - 1;
            cp_async16(smem_u32(&s.logit[0][ridx][lane * 4]), base + (size_t)r * KK);
        }
        asm volatile("cp.async.commit_group;");
    }
    __syncthreads();

    // ---- this thread's 128 transitions (column j) from SMEM, 64 f32x2 ----
    unsigned long long t2[64];
    #pragma unroll
    for (int m = 0; m < 64; ++m) {
        float2 tp = *reinterpret_cast<const float2*>(
            &s.transC[j * TC_STRIDE + 2 * m]);
        asm("mov.b64 %0, {%1, %2};" : "=l"(t2[m]) : "f"(tp.x), "f"(tp.y));
    }

    const unsigned sb0 = smem_u32(&s.spad[0][0]);
    const unsigned sb1 = smem_u32(&s.spad[1][0]);
    int pr = 0;

    // ================= forward pass (value-only; stores pre-logit h) ========
    for (int t = 1; t < len; ++t) {
        const int rel = t - 1;
        if ((rel & 15) == 0) {
            int g = rel >> 4;
            int base_row = 1 + (g + 1) * 16;
            int nb = (g + 1) & 1;
            const float* base = logits + (size_t)b * TT * KK + lane * 4;
            #pragma unroll
            for (int k = 0; k < 4; ++k) {
                int ridx = w + 4 * k;
                int r = base_row + ridx;  if (r > TT - 1) r = TT - 1;
                cp_async16(smem_u32(&s.logit[nb][ridx][lane * 4]),
                           base + (size_t)r * KK);
            }
            asm volatile("cp.async.commit_group;");
            asm volatile("cp.async.wait_group 1;");
            __syncthreads();
        }

        const unsigned sbr = pr ? sb1 : sb0;
        const float lg = s.logit[(rel >> 4) & 1][rel & 15][j];

        // 128 candidates: 32x broadcast LDS.128, 64x add.rn.f32x2, 8-acc tree
        float a0, a1, a2, a3, a4, a5, a6, a7;
        #pragma unroll
        for (int u = 0; u < 32; ++u) {
            unsigned long long p0, p1, c0, c1;
            asm volatile("ld.shared.v2.u64 {%0, %1}, [%2];"
                         : "=l"(p0), "=l"(p1) : "r"(sbr + 16 * u));
            asm("add.rn.f32x2 %0, %1, %2;" : "=l"(c0) : "l"(p0), "l"(t2[2 * u]));
            asm("add.rn.f32x2 %0, %1, %2;" : "=l"(c1) : "l"(p1), "l"(t2[2 * u + 1]));
            float x0, x1, x2, x3;
            asm("mov.b64 {%0, %1}, %2;" : "=f"(x0), "=f"(x1) : "l"(c0));
            asm("mov.b64 {%0, %1}, %2;" : "=f"(x2), "=f"(x3) : "l"(c1));
            if (u == 0)      { a0 = x0; a1 = x1; a2 = x2; a3 = x3; }
            else if (u == 1) { a4 = x0; a5 = x1; a6 = x2; a7 = x3; }
            else if (u & 1)  { a4 = fmaxf(a4, x0); a5 = fmaxf(a5, x1);
                               a6 = fmaxf(a6, x2); a7 = fmaxf(a7, x3); }
            else             { a0 = fmaxf(a0, x0); a1 = fmaxf(a1, x1);
                               a2 = fmaxf(a2, x2); a3 = fmaxf(a3, x3); }
        }
        float b0 = fmaxf(a0, a4), b1 = fmaxf(a1, a5);
        float b2 = fmaxf(a2, a6), b3 = fmaxf(a3, a7);
        float h = fmaxf(fmaxf(b0, b1), fmaxf(b2, b3));   // pre-logit max

        g_h[((size_t)b * TT + t) * KK + j] = h;           // exact target store
        s.spad[pr ^ 1][j] = h + lg;                       // live state
        pr ^= 1;
        __syncthreads();
    }
    asm volatile("cp.async.wait_all;");

    // ---- last tag = argmax_j final state (warp 0, first-index tie-break) ----
    if (w == 0) {
        const float* st = s.spad[pr];
        unsigned u0 = f32_mono_u32(st[4 * lane + 0]);
        unsigned u1 = f32_mono_u32(st[4 * lane + 1]);
        unsigned u2 = f32_mono_u32(st[4 * lane + 2]);
        unsigned u3 = f32_mono_u32(st[4 * lane + 3]);
        unsigned lm = max(max(u0, u1), max(u2, u3));
        unsigned gm = __reduce_max_sync(0xffffffffu, lm);
        unsigned cand = (u0 == gm) ? (unsigned)(4 * lane)
                      : (u1 == gm) ? (unsigned)(4 * lane + 1)
                      : (u2 == gm) ? (unsigned)(4 * lane + 2)
                      : (u3 == gm) ? (unsigned)(4 * lane + 3)
                      : 0xffffffffu;
        unsigned bi = __reduce_min_sync(0xffffffffu, cand);
        if (lane == 0) s.lasttag = (int)bi;
    }
    __syncthreads();
    const int lt = s.lasttag;

    // tail fill: tags[t] = last_tag for t >= len-1
    for (int t = len - 1 + tid; t < TT; t += NTHREADS) s.tags[t] = lt;

    // ================= backtrack: equality scan, double-buffered staging =====
    // tags[t] = first i with (h_t[i]+logit_t[i]) + T[i][cur] == h_{t+1}[cur]
    int cur = lt;
    int hi = len - 2;
    int bb2 = 0;
    if (hi >= 0) {
        {   // stage first block: h rows [lo..hi+1], logit rows [lo..hi]
            int lo2 = hi - (BR - 1); if (lo2 < 0) lo2 = 0;
            int nh = (hi + 1 - lo2 + 1) * KK;
            int nl = (hi - lo2 + 1) * KK;
            const float* hsrc = g_h    + ((size_t)b * TT + lo2) * KK;
            const float* lsrc = logits + ((size_t)b * TT + lo2) * KK;
            for (int idx = tid * 4; idx < nh; idx += NTHREADS * 4)
                cp_async16(smem_u32(&s.hblk[0][idx]), hsrc + idx);
            for (int idx = tid * 4; idx < nl; idx += NTHREADS * 4)
                cp_async16(smem_u32(&s.lblk[0][idx]), lsrc + idx);
            asm volatile("cp.async.commit_group;");
        }
        while (hi >= 0) {
            int lo = hi - (BR - 1); if (lo < 0) lo = 0;
            int nhi = lo - 1;
            if (nhi >= 0) {
                int lo2 = nhi - (BR - 1); if (lo2 < 0) lo2 = 0;
                int nh = (nhi + 1 - lo2 + 1) * KK;
                int nl = (nhi - lo2 + 1) * KK;
                const float* hsrc = g_h    + ((size_t)b * TT + lo2) * KK;
                const float* lsrc = logits + ((size_t)b * TT + lo2) * KK;
                for (int idx = tid * 4; idx < nh; idx += NTHREADS * 4)
                    cp_async16(smem_u32(&s.hblk[bb2 ^ 1][idx]), hsrc + idx);
                for (int idx = tid * 4; idx < nl; idx += NTHREADS * 4)
                    cp_async16(smem_u32(&s.lblk[bb2 ^ 1][idx]), lsrc + idx);
                asm volatile("cp.async.commit_group;");
                asm volatile("cp.async.wait_group 1;");
            } else {
                asm volatile("cp.async.wait_group 0;");
            }
            __syncthreads();

            if (tid < 32) {
                const float* hb = s.hblk[bb2];
                const float* lb = s.lblk[bb2];
                // sv = state_t row = h_t + logit_t (4 lanes' elements)
                float4 hv = *reinterpret_cast<const float4*>(
                    &hb[(hi - lo) * KK + 4 * lane]);
                float4 lv = *reinterpret_cast<const float4*>(
                    &lb[(hi - lo) * KK + 4 * lane]);
                float4 sv;
                sv.x = hv.x + lv.x;  sv.y = hv.y + lv.y;
                sv.z = hv.z + lv.z;  sv.w = hv.w + lv.w;
                for (int t = hi; t >= lo; --t) {
                    float target = hb[(t + 1 - lo) * KK + cur];  // broadcast LDS
                    float4 tv = *reinterpret_cast<const float4*>(
                        &s.transC[cur * TC_STRIDE + 4 * lane]);
                    float4 svn;
                    if (t > lo) {
                        float4 hn = *reinterpret_cast<const float4*>(
                            &hb[(t - 1 - lo) * KK + 4 * lane]);
                        float4 ln = *reinterpret_cast<const float4*>(
                            &lb[(t - 1 - lo) * KK + 4 * lane]);
                        svn.x = hn.x + ln.x;  svn.y = hn.y + ln.y;
                        svn.z = hn.z + ln.z;  svn.w = hn.w + ln.w;
                    }
                    unsigned m0 = __ballot_sync(0xffffffffu, sv.x + tv.x == target);
                    unsigned m1 = __ballot_sync(0xffffffffu, sv.y + tv.y == target);
                    unsigned m2 = __ballot_sync(0xffffffffu, sv.z + tv.z == target);
                    unsigned m3 = __ballot_sync(0xffffffffu, sv.w + tv.w == target);
                    int i0 = m0 ? 4 * (__ffs(m0) - 1) + 0 : 0x7fffffff;
                    int i1 = m1 ? 4 * (__ffs(m1) - 1) + 1 : 0x7fffffff;
                    int i2 = m2 ? 4 * (__ffs(m2) - 1) + 2 : 0x7fffffff;
                    int i3 = m3 ? 4 * (__ffs(m3) - 1) + 3 : 0x7fffffff;
                    cur = min(min(i0, i1), min(i2, i3));   // uniform across warp
                    if (lane == 0) s.tags[t] = cur;
                    sv = svn;
                }
            }
            __syncthreads();
            hi = nhi;
            bb2 ^= 1;
        }
    }
    __syncthreads();  // covers len==1 path (tags tail-fill -> output)

    // ================= one-hot output =================
    float* ob = out + (size_t)b * TT * KK;
    for (int it = 0; it < TT / 4; ++it) {
        int t = it * 4 + w;
        int tg = s.tags[t];
        float4 v;
        v.x = (tg == 4 * lane + 0) ? 1.0f : 0.0f;
        v.y = (tg == 4 * lane + 1) ? 1.0f : 0.0f;
        v.z = (tg == 4 * lane + 2) ? 1.0f : 0.0f;
        v.w = (tg == 4 * lane + 3) ? 1.0f : 0.0f;
        *reinterpret_cast<float4*>(ob + (size_t)t * KK + 4 * lane) = v;
    }
}

extern "C" void kernel_launch(void* const* d_in, const int* in_sizes, int n_in,
                              void* d_out, int out_size) {
    const float* logits = (const float*)d_in[0];
    const int*   lens   = (const int*)d_in[1];
    const float* trans  = (const float*)d_in[2];
    float*       out    = (float*)d_out;

    cudaFuncSetAttribute(crf_viterbi_kernel,
                         cudaFuncAttributeMaxDynamicSharedMemorySize,
                         (int)sizeof(SmemLayout));
    crf_viterbi_kernel<<<BB, NTHREADS, sizeof(SmemLayout)>>>(logits, lens, trans, out);
}

// round 11
// speedup vs baseline: 1.0062x; 1.0062x over previous
#include <cuda_runtime.h>
#include <cstdint>

// CRF Viterbi decode: B=128, T=1024, K=128 — THREE-KERNEL SPLIT for direct
// per-phase timing attribution (each launch shows separately in ncu).
// K1 forward: R6-proven math. One CTA (128 thr) per batch, thread per column,
//   32x broadcast LDS.128 state, 64x add.rn.f32x2 (transitions in regs),
//   8-acc FMNMX tree; post-logit state history -> 64MB scratch.
// K2 backtrack: one CTA per batch; warp 0 walks with double-buffered cp.async
//   64-row staging; IMNMX local argmax + integer REDUX (exact first-index
//   tie-break == jnp.argmax). Tags -> global.
// K3 one-hot: pure coalesced float4 stores.

#define BB 128
#define TT 1024
#define KK 128
#define TC_STRIDE 132
#define NTHREADS 128

__device__ float g_state[(size_t)BB * TT * KK];
__device__ int   g_tags[(size_t)BB * TT];

__device__ __forceinline__ unsigned smem_u32(const void* p) {
    return (unsigned)__cvta_generic_to_shared(p);
}
__device__ __forceinline__ void cp_async16(unsigned dst, const void* src) {
    asm volatile("cp.async.cg.shared.global [%0], [%1], 16;" :: "r"(dst), "l"(src));
}
__device__ __forceinline__ unsigned f32_mono_u32(float x) {
    unsigned b = __float_as_uint(x);
    return b ^ (unsigned)(((int)b >> 31) | 0x80000000);
}

// ===================== K1: forward =====================
struct __align__(16) FwdSmem {
    float trans[KK * KK];           // row-major transitions (reg-load source)
    float spad[2][KK];              // double-buffered state
    float logit[2][16][KK];         // double-buffered logit staging
};

__global__ void __launch_bounds__(NTHREADS, 1)
crf_fwd_kernel(const float* __restrict__ logits,
               const int*   __restrict__ lens,
               const float* __restrict__ trans)
{
    extern __shared__ char smraw[];
    FwdSmem& s = *reinterpret_cast<FwdSmem*>(smraw);

    const int b    = blockIdx.x;
    const int tid  = threadIdx.x;
    const int w    = tid >> 5;
    const int lane = tid & 31;
    const int j    = tid;
    const int len  = lens[b];

    // stage raw transitions (row-major) for register loads
    for (int idx = tid * 4; idx < KK * KK; idx += NTHREADS * 4)
        *reinterpret_cast<float4*>(&s.trans[idx]) =
            *reinterpret_cast<const float4*>(trans + idx);

    // init state = logits[b,0,:]
    {
        float v = logits[((size_t)b * TT) * KK + tid];
        s.spad[0][tid] = v;
        g_state[((size_t)b * TT) * KK + tid] = v;
    }

    // prologue: stage logit rows 1..16 into buffer 0
    {
        const float* base = logits + (size_t)b * TT * KK + lane * 4;
        #pragma unroll
        for (int k = 0; k < 4; ++k) {
            int ridx = w + 4 * k;
            int r = 1 + ridx;  if (r > TT - 1) r = TT - 1;
            cp_async16(smem_u32(&s.logit[0][ridx][lane * 4]), base + (size_t)r * KK);
        }
        asm volatile("cp.async.commit_group;");
    }
    __syncthreads();

    // this thread's 128 transitions (column j): T[i][j] = s.trans[i*KK+j]
    unsigned long long t2[64];
    #pragma unroll
    for (int m = 0; m < 64; ++m) {
        float lo = s.trans[(2 * m)     * KK + j];
        float hi = s.trans[(2 * m + 1) * KK + j];
        asm("mov.b64 %0, {%1, %2};" : "=l"(t2[m]) : "f"(lo), "f"(hi));
    }

    const unsigned sb0 = smem_u32(&s.spad[0][0]);
    const unsigned sb1 = smem_u32(&s.spad[1][0]);
    int pr = 0;

    for (int t = 1; t < len; ++t) {
        const int rel = t - 1;
        if ((rel & 15) == 0) {
            int g = rel >> 4;
            int base_row = 1 + (g + 1) * 16;
            int nb = (g + 1) & 1;
            const float* base = logits + (size_t)b * TT * KK + lane * 4;
            #pragma unroll
            for (int k = 0; k < 4; ++k) {
                int ridx = w + 4 * k;
                int r = base_row + ridx;  if (r > TT - 1) r = TT - 1;
                cp_async16(smem_u32(&s.logit[nb][ridx][lane * 4]),
                           base + (size_t)r * KK);
            }
            asm volatile("cp.async.commit_group;");
            asm volatile("cp.async.wait_group 1;");
            __syncthreads();
        }

        const unsigned sbr = pr ? sb1 : sb0;
        const float lg = s.logit[(rel >> 4) & 1][rel & 15][j];

        float a0, a1, a2, a3, a4, a5, a6, a7;
        #pragma unroll
        for (int u = 0; u < 32; ++u) {
            unsigned long long p0, p1, c0, c1;
            asm volatile("ld.shared.v2.u64 {%0, %1}, [%2];"
                         : "=l"(p0), "=l"(p1) : "r"(sbr + 16 * u));
            asm("add.rn.f32x2 %0, %1, %2;" : "=l"(c0) : "l"(p0), "l"(t2[2 * u]));
            asm("add.rn.f32x2 %0, %1, %2;" : "=l"(c1) : "l"(p1), "l"(t2[2 * u + 1]));
            float x0, x1, x2, x3;
            asm("mov.b64 {%0, %1}, %2;" : "=f"(x0), "=f"(x1) : "l"(c0));
            asm("mov.b64 {%0, %1}, %2;" : "=f"(x2), "=f"(x3) : "l"(c1));
            if (u == 0)      { a0 = x0; a1 = x1; a2 = x2; a3 = x3; }
            else if (u == 1) { a4 = x0; a5 = x1; a6 = x2; a7 = x3; }
            else if (u & 1)  { a4 = fmaxf(a4, x0); a5 = fmaxf(a5, x1);
                               a6 = fmaxf(a6, x2); a7 = fmaxf(a7, x3); }
            else             { a0 = fmaxf(a0, x0); a1 = fmaxf(a1, x1);
                               a2 = fmaxf(a2, x2); a3 = fmaxf(a3, x3); }
        }
        float b0 = fmaxf(a0, a4), b1 = fmaxf(a1, a5);
        float b2 = fmaxf(a2, a6), b3 = fmaxf(a3, a7);
        float best = fmaxf(fmaxf(b0, b1), fmaxf(b2, b3)) + lg;

        s.spad[pr ^ 1][j] = best;
        g_state[((size_t)b * TT + t) * KK + j] = best;
        pr ^= 1;
        __syncthreads();
    }
    asm volatile("cp.async.wait_all;");
}

// ===================== K2: backtrack =====================
struct __align__(16) BtSmem {
    float transC[KK * TC_STRIDE];   // transC[j*132 + i] = T[i][j]
    float block[2][64 * KK];        // double-buffered state-row staging
    int   lasttag;
};

__global__ void __launch_bounds__(NTHREADS, 1)
crf_bt_kernel(const int*   __restrict__ lens,
              const float* __restrict__ trans)
{
    extern __shared__ char smraw[];
    BtSmem& s = *reinterpret_cast<BtSmem*>(smraw);

    const int b    = blockIdx.x;
    const int tid  = threadIdx.x;
    const int lane = tid & 31;
    const int len  = lens[b];

    // transC staging
    for (int idx = tid * 4; idx < KK * KK; idx += NTHREADS * 4) {
        float4 v = *reinterpret_cast<const float4*>(trans + idx);
        int i  = idx >> 7;
        int jj = idx & (KK - 1);
        s.transC[(jj + 0) * TC_STRIDE + i] = v.x;
        s.transC[(jj + 1) * TC_STRIDE + i] = v.y;
        s.transC[(jj + 2) * TC_STRIDE + i] = v.z;
        s.transC[(jj + 3) * TC_STRIDE + i] = v.w;
    }

    // last tag = argmax_j final state (warp 0, first-index tie-break)
    if (tid < 32) {
        const float* st = g_state + ((size_t)b * TT + (len - 1)) * KK;
        unsigned u0 = f32_mono_u32(st[4 * lane + 0]);
        unsigned u1 = f32_mono_u32(st[4 * lane + 1]);
        unsigned u2 = f32_mono_u32(st[4 * lane + 2]);
        unsigned u3 = f32_mono_u32(st[4 * lane + 3]);
        unsigned lm = max(max(u0, u1), max(u2, u3));
        unsigned gm = __reduce_max_sync(0xffffffffu, lm);
        unsigned cand = (u0 == gm) ? (unsigned)(4 * lane)
                      : (u1 == gm) ? (unsigned)(4 * lane + 1)
                      : (u2 == gm) ? (unsigned)(4 * lane + 2)
                      : (u3 == gm) ? (unsigned)(4 * lane + 3)
                      : 0xffffffffu;
        unsigned bi = __reduce_min_sync(0xffffffffu, cand);
        if (lane == 0) s.lasttag = (int)bi;
    }
    __syncthreads();
    const int lt = s.lasttag;

    // tail fill
    for (int t = len - 1 + tid; t < TT; t += NTHREADS)
        g_tags[(size_t)b * TT + t] = lt;

    int cur = lt;
    int hi = len - 2;
    int bb2 = 0;
    if (hi >= 0) {
        {   // stage first block
            int lo2 = hi - 63; if (lo2 < 0) lo2 = 0;
            int n = (hi - lo2 + 1) * KK;
            const float* src = g_state + ((size_t)b * TT + lo2) * KK;
            for (int idx = tid * 4; idx < n; idx += NTHREADS * 4)
                cp_async16(smem_u32(&s.block[0][idx]), src + idx);
            asm volatile("cp.async.commit_group;");
        }
        while (hi >= 0) {
            int lo = hi - 63; if (lo < 0) lo = 0;
            int nhi = lo - 1;
            if (nhi >= 0) {
                int lo2 = nhi - 63; if (lo2 < 0) lo2 = 0;
                int n = (nhi - lo2 + 1) * KK;
                const float* src = g_state + ((size_t)b * TT + lo2) * KK;
                for (int idx = tid * 4; idx < n; idx += NTHREADS * 4)
                    cp_async16(smem_u32(&s.block[bb2 ^ 1][idx]), src + idx);
                asm volatile("cp.async.commit_group;");
                asm volatile("cp.async.wait_group 1;");
            } else {
                asm volatile("cp.async.wait_group 0;");
            }
            __syncthreads();

            if (tid < 32) {
                const float* blk = s.block[bb2];
                float4 sv = *reinterpret_cast<const float4*>(
                    &blk[(hi - lo) * KK + 4 * lane]);
                for (int t = hi; t >= lo; --t) {
                    float4 tv = *reinterpret_cast<const float4*>(
                        &s.transC[cur * TC_STRIDE + 4 * lane]);
                    float4 svn;
                    if (t > lo)
                        svn = *reinterpret_cast<const float4*>(
                            &blk[(t - 1 - lo) * KK + 4 * lane]);
                    unsigned u0 = f32_mono_u32(sv.x + tv.x);
                    unsigned u1 = f32_mono_u32(sv.y + tv.y);
                    unsigned u2 = f32_mono_u32(sv.z + tv.z);
                    unsigned u3 = f32_mono_u32(sv.w + tv.w);
                    unsigned lm = max(max(u0, u1), max(u2, u3));
                    unsigned gm = __reduce_max_sync(0xffffffffu, lm);
                    unsigned cand = (u0 == gm) ? (unsigned)(4 * lane)
                                  : (u1 == gm) ? (unsigned)(4 * lane + 1)
                                  : (u2 == gm) ? (unsigned)(4 * lane + 2)
                                  : (u3 == gm) ? (unsigned)(4 * lane + 3)
                                  : 0xffffffffu;
                    cur = (int)__reduce_min_sync(0xffffffffu, cand);
                    if (lane == 0) g_tags[(size_t)b * TT + t] = cur;
                    sv = svn;
                }
            }
            __syncthreads();
            hi = nhi;
            bb2 ^= 1;
        }
    }
}

// ===================== K3: one-hot output =====================
__global__ void __launch_bounds__(NTHREADS, 1)
crf_onehot_kernel(float* __restrict__ out)
{
    const int b    = blockIdx.x;
    const int tid  = threadIdx.x;
    const int w    = tid >> 5;
    const int lane = tid & 31;
    float* ob = out + (size_t)b * TT * KK;
    const int* tg_row = g_tags + (size_t)b * TT;
    for (int it = 0; it < TT / 4; ++it) {
        int t = it * 4 + w;
        int tg = tg_row[t];
        float4 v;
        v.x = (tg == 4 * lane + 0) ? 1.0f : 0.0f;
        v.y = (tg == 4 * lane + 1) ? 1.0f : 0.0f;
        v.z = (tg == 4 * lane + 2) ? 1.0f : 0.0f;
        v.w = (tg == 4 * lane + 3) ? 1.0f : 0.0f;
        *reinterpret_cast<float4*>(ob + (size_t)t * KK + 4 * lane) = v;
    }
}

extern "C" void kernel_launch(void* const* d_in, const int* in_sizes, int n_in,
                              void* d_out, int out_size) {
    const float* logits = (const float*)d_in[0];
    const int*   lens   = (const int*)d_in[1];
    const float* trans  = (const float*)d_in[2];
    float*       out    = (float*)d_out;

    cudaFuncSetAttribute(crf_fwd_kernel,
                         cudaFuncAttributeMaxDynamicSharedMemorySize,
                         (int)sizeof(FwdSmem));
    cudaFuncSetAttribute(crf_bt_kernel,
                         cudaFuncAttributeMaxDynamicSharedMemorySize,
                         (int)sizeof(BtSmem));

    crf_fwd_kernel<<<BB, NTHREADS, sizeof(FwdSmem)>>>(logits, lens, trans);
    crf_bt_kernel<<<BB, NTHREADS, sizeof(BtSmem)>>>(lens, trans);
    crf_onehot_kernel<<<BB, NTHREADS>>>(out);
}